// round 12
// baseline (speedup 1.0000x reference)
#include <cuda_runtime.h>
#include <cuda_fp16.h>
#include <math.h>

#define NN 100000
#define NE 3200000
#define NG 64
#define D 32
#define INF 128
#define NPAD 102400        // 1024 threads * 100 counters
#define FUSED_BLOCKS 1480  // 148 SMs * 10 CTAs: one wave
#define G0_TILES 1563      // ceil(NN/64)
#define SC_CHUNKS 12500    // NE/4/64

// ---- scratch (zero-initialized at module load; scan_all re-zeros per call) ----
__device__ __half g_rhsH[NN * D];   // fp16 gather buffer (64B rows)
__device__ float  g_self[NN * D];
__device__ float  g_h[NN * D];
__device__ float  g_pool[NG * D];
__device__ int    g_counts[NPAD];
__device__ int    g_offs[NPAD + 1];
__device__ int    g_cursor[NPAD];
__device__ int    g_csrc[NE];

// ------------------------------------------------------------------
__global__ void hist_kernel(const int* __restrict__ dst) {
    int i = blockIdx.x * blockDim.x + threadIdx.x;
    int b = i * 4;
    if (b < NE) {
        int4 d = *(const int4*)&dst[b];
        atomicAdd(&g_counts[d.x], 1);
        atomicAdd(&g_counts[d.y], 1);
        atomicAdd(&g_counts[d.z], 1);
        atomicAdd(&g_counts[d.w], 1);
    }
}

// single-block scan; also re-zeros g_counts and zeros g_pool for this call.
__global__ void __launch_bounds__(1024) scan_all() {
    const int CH = 100;
    int tid = threadIdx.x;
    int lane = tid & 31, wid = tid >> 5;
    int base = tid * CH;
    int s = 0;
    int cnt[CH];
#pragma unroll
    for (int i = 0; i < CH; i += 4) {
        int4 v = *(const int4*)&g_counts[base + i];
        cnt[i] = v.x; cnt[i + 1] = v.y; cnt[i + 2] = v.z; cnt[i + 3] = v.w;
        s += v.x + v.y + v.z + v.w;
    }
    int pre = s;
#pragma unroll
    for (int dd = 1; dd < 32; dd <<= 1) {
        int t = __shfl_up_sync(0xffffffffu, pre, dd);
        if (lane >= dd) pre += t;
    }
    __shared__ int wsum[32];
    if (lane == 31) wsum[wid] = pre;
    __syncthreads();
    if (wid == 0) {
        int v = wsum[lane];
        int p = v;
#pragma unroll
        for (int dd = 1; dd < 32; dd <<= 1) {
            int t = __shfl_up_sync(0xffffffffu, p, dd);
            if (lane >= dd) p += t;
        }
        wsum[lane] = p - v;
    }
    __syncthreads();
    int run = wsum[wid] + (pre - s);
    const int4 z4 = make_int4(0, 0, 0, 0);
#pragma unroll
    for (int i = 0; i < CH; i += 4) {
        int4 o;
        o.x = run; run += cnt[i];
        o.y = run; run += cnt[i + 1];
        o.z = run; run += cnt[i + 2];
        o.w = run; run += cnt[i + 3];
        *(int4*)&g_offs[base + i]   = o;
        *(int4*)&g_cursor[base + i] = o;
        *(int4*)&g_counts[base + i] = z4;
    }
    if (tid < NG * D / 2) *(float2*)&g_pool[tid * 2] = make_float2(0.f, 0.f);
}

// ------------------------------------------------------------------
// Store helper: 16 fp32 accumulators -> 16 fp16 (two uint4 = 32B)
__device__ __forceinline__ void store_rhs_fp16(__half* dstp, const float* a) {
    __align__(16) __half2 hp[8];
#pragma unroll
    for (int j = 0; j < 8; j++)
        hp[j] = __floats2half2_rn(a[2 * j], a[2 * j + 1]);
    *(uint4*)&dstp[0] = *(uint4*)&hp[0];
    *(uint4*)&dstp[8] = *(uint4*)&hp[4];
}

// One 64-node gemm0 tile (64 threads; thread = 4 nodes x 16 cols; W per k-tile).
__device__ __forceinline__ void gemm0_tile(int tile,
                                           const float* __restrict__ x,
                                           const float* __restrict__ Wn0,
                                           const float* __restrict__ Ws0,
                                           float Wsh[32][64], float xs[64][33]) {
    int tid = threadIdx.x;
    int n0 = tile * 64;
    int ng = tid >> 2, cg = tid & 3;
    int c0 = cg * 16;
    float acc[4][16];
#pragma unroll
    for (int i = 0; i < 4; i++)
#pragma unroll
        for (int j = 0; j < 16; j++) acc[i][j] = 0.f;

    for (int kt = 0; kt < 4; kt++) {
        __syncthreads();
        for (int idx = tid; idx < 32 * 32; idx += 64) {
            int k = idx >> 5, c = idx & 31;
            Wsh[k][c]      = Wn0[kt * 1024 + idx];
            Wsh[k][c + 32] = Ws0[kt * 1024 + idx];
        }
        for (int idx = tid; idx < 64 * 32; idx += 64) {
            int nl = idx >> 5, j = idx & 31;
            int n = n0 + nl;
            xs[nl][j] = (n < NN) ? x[n * INF + kt * 32 + j] : 0.f;
        }
        __syncthreads();
#pragma unroll 4
        for (int k = 0; k < 32; k++) {
            float xv[4];
#pragma unroll
            for (int i = 0; i < 4; i++) xv[i] = xs[ng * 4 + i][k];
            const float* wrow = &Wsh[k][c0];
            float4 w0 = *(const float4*)&wrow[0];
            float4 w1 = *(const float4*)&wrow[4];
            float4 w2 = *(const float4*)&wrow[8];
            float4 w3 = *(const float4*)&wrow[12];
#pragma unroll
            for (int i = 0; i < 4; i++) {
                float xi = xv[i];
                acc[i][0]  = fmaf(xi, w0.x, acc[i][0]);
                acc[i][1]  = fmaf(xi, w0.y, acc[i][1]);
                acc[i][2]  = fmaf(xi, w0.z, acc[i][2]);
                acc[i][3]  = fmaf(xi, w0.w, acc[i][3]);
                acc[i][4]  = fmaf(xi, w1.x, acc[i][4]);
                acc[i][5]  = fmaf(xi, w1.y, acc[i][5]);
                acc[i][6]  = fmaf(xi, w1.z, acc[i][6]);
                acc[i][7]  = fmaf(xi, w1.w, acc[i][7]);
                acc[i][8]  = fmaf(xi, w2.x, acc[i][8]);
                acc[i][9]  = fmaf(xi, w2.y, acc[i][9]);
                acc[i][10] = fmaf(xi, w2.z, acc[i][10]);
                acc[i][11] = fmaf(xi, w2.w, acc[i][11]);
                acc[i][12] = fmaf(xi, w3.x, acc[i][12]);
                acc[i][13] = fmaf(xi, w3.y, acc[i][13]);
                acc[i][14] = fmaf(xi, w3.z, acc[i][14]);
                acc[i][15] = fmaf(xi, w3.w, acc[i][15]);
            }
        }
    }
#pragma unroll
    for (int i = 0; i < 4; i++) {
        int n = n0 + ng * 4 + i;
        if (n >= NN) break;
        if (cg < 2) {
            store_rhs_fp16(&g_rhsH[n * D + c0], acc[i]);
        } else {
            float* dstp = &g_self[n * D + (c0 - 32)];
#pragma unroll
            for (int j = 0; j < 4; j++) {
                float4 f = make_float4(acc[i][4 * j], acc[i][4 * j + 1],
                                       acc[i][4 * j + 2], acc[i][4 * j + 3]);
                *(float4*)&dstp[4 * j] = f;
            }
        }
    }
}

// Fused: one-wave kernel; each block does its gemm0 tiles, then scatter chunks.
// gemm0 and scatter are data-independent; packing them overlaps FMA-bound and
// L2-atomic-bound work in the same wave.
__global__ void __launch_bounds__(64, 10) fused_g0_scatter(const float* __restrict__ x,
                                                           const float* __restrict__ Wn0,
                                                           const float* __restrict__ Ws0,
                                                           const int* __restrict__ src,
                                                           const int* __restrict__ dst) {
    __shared__ float Wsh[32][64];
    __shared__ float xs[64][33];
    int tid = threadIdx.x;

    for (int tile = blockIdx.x; tile < G0_TILES; tile += FUSED_BLOCKS)
        gemm0_tile(tile, x, Wn0, Ws0, Wsh, xs);

    for (int c = blockIdx.x; c < SC_CHUNKS; c += FUSED_BLOCKS) {
        int b = (c * 64 + tid) * 4;   // always < NE (12500*64*4 == NE)
        int4 s4 = *(const int4*)&src[b];
        int4 d4 = *(const int4*)&dst[b];
        int p;
        p = atomicAdd(&g_cursor[d4.x], 1); g_csrc[p] = s4.x;
        p = atomicAdd(&g_cursor[d4.y], 1); g_csrc[p] = s4.y;
        p = atomicAdd(&g_cursor[d4.z], 1); g_csrc[p] = s4.z;
        p = atomicAdd(&g_cursor[d4.w], 1); g_csrc[p] = s4.w;
    }
}

// Layers 1..3: rhsH = fp16(h@Wn_l), self = h@Ws_l  (register blocked, K=32).
__global__ void __launch_bounds__(64, 10) gemm_small_kernel(const float* __restrict__ Wn_l,
                                                            const float* __restrict__ Ws_l) {
    __shared__ float Wsh[D][64];
    __shared__ float xs[64][33];
    int tid = threadIdx.x;
    for (int idx = tid; idx < D * D; idx += 64) {
        int k = idx >> 5, c = idx & 31;
        Wsh[k][c]      = Wn_l[idx];
        Wsh[k][c + 32] = Ws_l[idx];
    }
    int n0 = blockIdx.x * 64;
    for (int idx = tid; idx < 64 * 32; idx += 64) {
        int nl = idx >> 5, j = idx & 31;
        int n = n0 + nl;
        xs[nl][j] = (n < NN) ? g_h[n * D + j] : 0.f;
    }
    __syncthreads();
    int ng = tid >> 2, cg = tid & 3;
    int c0 = cg * 16;
    float acc[4][16];
#pragma unroll
    for (int i = 0; i < 4; i++)
#pragma unroll
        for (int j = 0; j < 16; j++) acc[i][j] = 0.f;

#pragma unroll 4
    for (int k = 0; k < 32; k++) {
        float xv[4];
#pragma unroll
        for (int i = 0; i < 4; i++) xv[i] = xs[ng * 4 + i][k];
        const float* wrow = &Wsh[k][c0];
        float4 w0 = *(const float4*)&wrow[0];
        float4 w1 = *(const float4*)&wrow[4];
        float4 w2 = *(const float4*)&wrow[8];
        float4 w3 = *(const float4*)&wrow[12];
#pragma unroll
        for (int i = 0; i < 4; i++) {
            float xi = xv[i];
            acc[i][0]  = fmaf(xi, w0.x, acc[i][0]);
            acc[i][1]  = fmaf(xi, w0.y, acc[i][1]);
            acc[i][2]  = fmaf(xi, w0.z, acc[i][2]);
            acc[i][3]  = fmaf(xi, w0.w, acc[i][3]);
            acc[i][4]  = fmaf(xi, w1.x, acc[i][4]);
            acc[i][5]  = fmaf(xi, w1.y, acc[i][5]);
            acc[i][6]  = fmaf(xi, w1.z, acc[i][6]);
            acc[i][7]  = fmaf(xi, w1.w, acc[i][7]);
            acc[i][8]  = fmaf(xi, w2.x, acc[i][8]);
            acc[i][9]  = fmaf(xi, w2.y, acc[i][9]);
            acc[i][10] = fmaf(xi, w2.z, acc[i][10]);
            acc[i][11] = fmaf(xi, w2.w, acc[i][11]);
            acc[i][12] = fmaf(xi, w3.x, acc[i][12]);
            acc[i][13] = fmaf(xi, w3.y, acc[i][13]);
            acc[i][14] = fmaf(xi, w3.z, acc[i][14]);
            acc[i][15] = fmaf(xi, w3.w, acc[i][15]);
        }
    }
#pragma unroll
    for (int i = 0; i < 4; i++) {
        int n = n0 + ng * 4 + i;
        if (n >= NN) break;
        if (cg < 2) {
            store_rhs_fp16(&g_rhsH[n * D + c0], acc[i]);
        } else {
            float* dstp = &g_self[n * D + (c0 - 32)];
#pragma unroll
            for (int j = 0; j < 4; j++) {
                float4 f = make_float4(acc[i][4 * j], acc[i][4 * j + 1],
                                       acc[i][4 * j + 2], acc[i][4 * j + 3]);
                *(float4*)&dstp[4 * j] = f;
            }
        }
    }
}

// ------------------------------------------------------------------
// Aggregation (R8-verified): warp per node; 8 edges per warp-LDG, plain cached loads.
// Lane role: eg = lane>>2 (edge slot 0..7), q = lane&3 (dims 8q..8q+7 as uint4).
__device__ __forceinline__ void acc8(uint4 v, float* f) {
    const __half2* h = (const __half2*)&v;
#pragma unroll
    for (int j = 0; j < 4; j++) {
        float2 t = __half22float2(h[j]);
        f[2 * j]     += t.x;
        f[2 * j + 1] += t.y;
    }
}

__global__ void __launch_bounds__(256) agg_kernel(const float* __restrict__ bn) {
    int tid = threadIdx.x;
    int w = (blockIdx.x * blockDim.x + tid) >> 5;
    if (w >= NN) return;
    int lane = tid & 31;
    int eg = lane >> 2, q = lane & 3;
    const uint4* __restrict__ rhs4 = (const uint4*)g_rhsH;   // 4 uint4 per row

    int beg = g_offs[w], end = g_offs[w + 1];
    float f[8];
#pragma unroll
    for (int j = 0; j < 8; j++) f[j] = 0.f;

    int e = beg;
    while (e + 16 <= end) {
        int s0 = g_csrc[e + eg];
        int s1 = g_csrc[e + 8 + eg];
        uint4 v0 = rhs4[s0 * 4 + q];
        uint4 v1 = rhs4[s1 * 4 + q];
        acc8(v0, f);
        acc8(v1, f);
        e += 16;
    }
    while (e + 8 <= end) {
        int s = g_csrc[e + eg];
        uint4 v = rhs4[s * 4 + q];
        acc8(v, f);
        e += 8;
    }
    int rem = end - e;
    if (eg < rem) {
        int s = g_csrc[e + eg];
        uint4 v = rhs4[s * 4 + q];
        acc8(v, f);
    }

#pragma unroll
    for (int j = 0; j < 8; j++) {
        f[j] += __shfl_xor_sync(0xffffffffu, f[j], 4);
        f[j] += __shfl_xor_sync(0xffffffffu, f[j], 8);
        f[j] += __shfl_xor_sync(0xffffffffu, f[j], 16);
    }

    if (lane < 4) {
        int base = w * D + 8 * lane;
        float4 s0 = *(const float4*)&g_self[base];
        float4 s1 = *(const float4*)&g_self[base + 4];
        float4 b0 = *(const float4*)&bn[8 * lane];
        float4 b1 = *(const float4*)&bn[8 * lane + 4];
        float4 o0, o1;
        o0.x = fmaxf(f[0] + s0.x + b0.x, 0.f);
        o0.y = fmaxf(f[1] + s0.y + b0.y, 0.f);
        o0.z = fmaxf(f[2] + s0.z + b0.z, 0.f);
        o0.w = fmaxf(f[3] + s0.w + b0.w, 0.f);
        o1.x = fmaxf(f[4] + s1.x + b1.x, 0.f);
        o1.y = fmaxf(f[5] + s1.y + b1.y, 0.f);
        o1.z = fmaxf(f[6] + s1.z + b1.z, 0.f);
        o1.w = fmaxf(f[7] + s1.w + b1.w, 0.f);
        *(float4*)&g_h[base]     = o0;
        *(float4*)&g_h[base + 4] = o1;
    }
}

// ------------------------------------------------------------------
__global__ void __launch_bounds__(256) pool_kernel(const int* __restrict__ gid) {
    __shared__ float ps[NG * D];
    int tid = threadIdx.x;
    for (int i = tid; i < NG * D; i += 256) ps[i] = 0.f;
    __syncthreads();
    int d = tid & 31;
    int base = blockIdx.x * 1024;
    for (int i = tid >> 5; i < 1024; i += 8) {
        int n = base + i;
        if (n < NN) atomicAdd(&ps[gid[n] * D + d], g_h[n * D + d]);
    }
    __syncthreads();
    for (int i = tid; i < NG * D; i += 256) {
        float v = ps[i];
        if (v != 0.f) atomicAdd(&g_pool[i], v);
    }
}

__global__ void mlp_kernel(const float* __restrict__ Wfc1, const float* __restrict__ bfc1,
                           const float* __restrict__ Wout, const float* __restrict__ bout,
                           float* __restrict__ out) {
    int g = threadIdx.x;
    if (g >= NG) return;
    float hv[D];
#pragma unroll
    for (int k = 0; k < D; k++) hv[k] = g_pool[g * D + k];
    float h2[8];
#pragma unroll
    for (int j = 0; j < 8; j++) {
        float s = bfc1[j];
#pragma unroll
        for (int k = 0; k < D; k++) s = fmaf(hv[k], Wfc1[k * 8 + j], s);
        h2[j] = fmaxf(s, 0.f);
    }
    float o[4];
    float m = -1e30f;
#pragma unroll
    for (int j = 0; j < 4; j++) {
        float s = bout[j];
#pragma unroll
        for (int k = 0; k < 8; k++) s = fmaf(h2[k], Wout[k * 4 + j], s);
        o[j] = fmaxf(s, 0.f);
        if (o[j] > m) m = o[j];
    }
    float e[4]; float sum = 0.f;
#pragma unroll
    for (int j = 0; j < 4; j++) { e[j] = expf(o[j] - m); sum += e[j]; }
#pragma unroll
    for (int j = 0; j < 4; j++) out[g * 4 + j] = e[j] / sum;
}

// ------------------------------------------------------------------
extern "C" void kernel_launch(void* const* d_in, const int* in_sizes, int n_in,
                              void* d_out, int out_size) {
    const float* x    = (const float*)d_in[0];
    const float* Wn0  = (const float*)d_in[1];
    const float* bn0  = (const float*)d_in[2];
    const float* Ws0  = (const float*)d_in[3];
    const float* Wn   = (const float*)d_in[4];
    const float* bn   = (const float*)d_in[5];
    const float* Ws   = (const float*)d_in[6];
    const float* Wfc1 = (const float*)d_in[7];
    const float* bfc1 = (const float*)d_in[8];
    const float* Wout = (const float*)d_in[9];
    const float* bout = (const float*)d_in[10];
    const int*   src  = (const int*)d_in[11];
    const int*   dst  = (const int*)d_in[12];
    const int*   gid  = (const int*)d_in[13];
    float* out = (float*)d_out;

    hist_kernel<<<(NE / 4 + 255) / 256, 256>>>(dst);
    scan_all<<<1, 1024>>>();
    fused_g0_scatter<<<FUSED_BLOCKS, 64>>>(x, Wn0, Ws0, src, dst);

    agg_kernel<<<(NN * 32 + 255) / 256, 256>>>(bn0);

    for (int l = 0; l < 3; l++) {
        gemm_small_kernel<<<(NN + 63) / 64, 64>>>(Wn + l * D * D, Ws + l * D * D);
        agg_kernel<<<(NN * 32 + 255) / 256, 256>>>(bn + l * D);
    }

    pool_kernel<<<(NN + 1023) / 1024, 256>>>(gid);
    mlp_kernel<<<1, 64>>>(Wfc1, bfc1, Wout, bout, out);
}

// round 13
// speedup vs baseline: 1.0426x; 1.0426x over previous
#include <cuda_runtime.h>
#include <cuda_fp16.h>
#include <math.h>

#define NN 100000
#define NE 3200000
#define NG 64
#define D 32
#define INF 128
#define NPAD 102400   // 1024 threads * 100 counters

// ---- scratch (zero-initialized at module load; scan_all re-zeros per call) ----
__device__ __half g_rhsH[NN * D];   // fp16 gather buffer (64B rows)
__device__ float  g_self[NN * D];
__device__ float  g_h[NN * D];
__device__ float  g_pool[NG * D];
__device__ int    g_counts[NPAD];
__device__ int    g_offs[NPAD + 1];
__device__ int    g_cursor[NPAD];
__device__ int    g_csrc[NE];

// ------------------------------------------------------------------
__global__ void hist_kernel(const int* __restrict__ dst) {
    int i = blockIdx.x * blockDim.x + threadIdx.x;
    int b = i * 4;
    if (b < NE) {
        int4 d = *(const int4*)&dst[b];
        atomicAdd(&g_counts[d.x], 1);
        atomicAdd(&g_counts[d.y], 1);
        atomicAdd(&g_counts[d.z], 1);
        atomicAdd(&g_counts[d.w], 1);
    }
}

// single-block scan; also re-zeros g_counts and zeros g_pool for this call.
__global__ void __launch_bounds__(1024) scan_all() {
    const int CH = 100;
    int tid = threadIdx.x;
    int lane = tid & 31, wid = tid >> 5;
    int base = tid * CH;
    int s = 0;
    int cnt[CH];
#pragma unroll
    for (int i = 0; i < CH; i += 4) {
        int4 v = *(const int4*)&g_counts[base + i];
        cnt[i] = v.x; cnt[i + 1] = v.y; cnt[i + 2] = v.z; cnt[i + 3] = v.w;
        s += v.x + v.y + v.z + v.w;
    }
    int pre = s;
#pragma unroll
    for (int dd = 1; dd < 32; dd <<= 1) {
        int t = __shfl_up_sync(0xffffffffu, pre, dd);
        if (lane >= dd) pre += t;
    }
    __shared__ int wsum[32];
    if (lane == 31) wsum[wid] = pre;
    __syncthreads();
    if (wid == 0) {
        int v = wsum[lane];
        int p = v;
#pragma unroll
        for (int dd = 1; dd < 32; dd <<= 1) {
            int t = __shfl_up_sync(0xffffffffu, p, dd);
            if (lane >= dd) p += t;
        }
        wsum[lane] = p - v;
    }
    __syncthreads();
    int run = wsum[wid] + (pre - s);
    const int4 z4 = make_int4(0, 0, 0, 0);
#pragma unroll
    for (int i = 0; i < CH; i += 4) {
        int4 o;
        o.x = run; run += cnt[i];
        o.y = run; run += cnt[i + 1];
        o.z = run; run += cnt[i + 2];
        o.w = run; run += cnt[i + 3];
        *(int4*)&g_offs[base + i]   = o;
        *(int4*)&g_cursor[base + i] = o;
        *(int4*)&g_counts[base + i] = z4;
    }
    if (tid < NG * D / 2) *(float2*)&g_pool[tid * 2] = make_float2(0.f, 0.f);
}

__global__ void scatter_kernel(const int* __restrict__ src, const int* __restrict__ dst) {
    int i = blockIdx.x * blockDim.x + threadIdx.x;
    int b = i * 4;
    if (b < NE) {
        int4 s4 = *(const int4*)&src[b];
        int4 d4 = *(const int4*)&dst[b];
        int p;
        p = atomicAdd(&g_cursor[d4.x], 1); g_csrc[p] = s4.x;
        p = atomicAdd(&g_cursor[d4.y], 1); g_csrc[p] = s4.y;
        p = atomicAdd(&g_cursor[d4.z], 1); g_csrc[p] = s4.z;
        p = atomicAdd(&g_cursor[d4.w], 1); g_csrc[p] = s4.w;
    }
}

// ------------------------------------------------------------------
// Store helper: 16 fp32 accumulators -> 16 fp16 (two uint4 = 32B)
__device__ __forceinline__ void store_rhs_fp16(__half* dstp, const float* a) {
    __align__(16) __half2 hp[8];
#pragma unroll
    for (int j = 0; j < 8; j++)
        hp[j] = __floats2half2_rn(a[2 * j], a[2 * j + 1]);
    *(uint4*)&dstp[0] = *(uint4*)&hp[0];
    *(uint4*)&dstp[8] = *(uint4*)&hp[4];
}

// Layer 0 (R11-verified): 64 thr, 64 nodes/block; 4 nodes x 16 cols/thread;
// W staged per 32-k tile; reg-capped for 10 CTAs/SM.
__global__ void __launch_bounds__(64, 10) gemm0_kernel(const float* __restrict__ x,
                                                       const float* __restrict__ Wn0,
                                                       const float* __restrict__ Ws0) {
    __shared__ float Wsh[32][64];
    __shared__ float xs[64][33];
    int tid = threadIdx.x;
    int n0 = blockIdx.x * 64;
    int ng = tid >> 2, cg = tid & 3;
    int c0 = cg * 16;
    float acc[4][16];
#pragma unroll
    for (int i = 0; i < 4; i++)
#pragma unroll
        for (int j = 0; j < 16; j++) acc[i][j] = 0.f;

    for (int kt = 0; kt < 4; kt++) {
        __syncthreads();
        for (int idx = tid; idx < 32 * 32; idx += 64) {
            int k = idx >> 5, c = idx & 31;
            Wsh[k][c]      = Wn0[kt * 1024 + idx];
            Wsh[k][c + 32] = Ws0[kt * 1024 + idx];
        }
        for (int idx = tid; idx < 64 * 32; idx += 64) {
            int nl = idx >> 5, j = idx & 31;
            int n = n0 + nl;
            xs[nl][j] = (n < NN) ? x[n * INF + kt * 32 + j] : 0.f;
        }
        __syncthreads();
#pragma unroll 4
        for (int k = 0; k < 32; k++) {
            float xv[4];
#pragma unroll
            for (int i = 0; i < 4; i++) xv[i] = xs[ng * 4 + i][k];
            const float* wrow = &Wsh[k][c0];
            float4 w0 = *(const float4*)&wrow[0];
            float4 w1 = *(const float4*)&wrow[4];
            float4 w2 = *(const float4*)&wrow[8];
            float4 w3 = *(const float4*)&wrow[12];
#pragma unroll
            for (int i = 0; i < 4; i++) {
                float xi = xv[i];
                acc[i][0]  = fmaf(xi, w0.x, acc[i][0]);
                acc[i][1]  = fmaf(xi, w0.y, acc[i][1]);
                acc[i][2]  = fmaf(xi, w0.z, acc[i][2]);
                acc[i][3]  = fmaf(xi, w0.w, acc[i][3]);
                acc[i][4]  = fmaf(xi, w1.x, acc[i][4]);
                acc[i][5]  = fmaf(xi, w1.y, acc[i][5]);
                acc[i][6]  = fmaf(xi, w1.z, acc[i][6]);
                acc[i][7]  = fmaf(xi, w1.w, acc[i][7]);
                acc[i][8]  = fmaf(xi, w2.x, acc[i][8]);
                acc[i][9]  = fmaf(xi, w2.y, acc[i][9]);
                acc[i][10] = fmaf(xi, w2.z, acc[i][10]);
                acc[i][11] = fmaf(xi, w2.w, acc[i][11]);
                acc[i][12] = fmaf(xi, w3.x, acc[i][12]);
                acc[i][13] = fmaf(xi, w3.y, acc[i][13]);
                acc[i][14] = fmaf(xi, w3.z, acc[i][14]);
                acc[i][15] = fmaf(xi, w3.w, acc[i][15]);
            }
        }
    }
#pragma unroll
    for (int i = 0; i < 4; i++) {
        int n = n0 + ng * 4 + i;
        if (n >= NN) break;
        if (cg < 2) {
            store_rhs_fp16(&g_rhsH[n * D + c0], acc[i]);
        } else {
            float* dstp = &g_self[n * D + (c0 - 32)];
#pragma unroll
            for (int j = 0; j < 4; j++) {
                float4 f = make_float4(acc[i][4 * j], acc[i][4 * j + 1],
                                       acc[i][4 * j + 2], acc[i][4 * j + 3]);
                *(float4*)&dstp[4 * j] = f;
            }
        }
    }
}

// Layers 1..3: rhsH = fp16(h@Wn_l), self = h@Ws_l  (register blocked, K=32).
__global__ void __launch_bounds__(64, 10) gemm_small_kernel(const float* __restrict__ Wn_l,
                                                            const float* __restrict__ Ws_l) {
    __shared__ float Wsh[D][64];
    __shared__ float xs[64][33];
    int tid = threadIdx.x;
    for (int idx = tid; idx < D * D; idx += 64) {
        int k = idx >> 5, c = idx & 31;
        Wsh[k][c]      = Wn_l[idx];
        Wsh[k][c + 32] = Ws_l[idx];
    }
    int n0 = blockIdx.x * 64;
    for (int idx = tid; idx < 64 * 32; idx += 64) {
        int nl = idx >> 5, j = idx & 31;
        int n = n0 + nl;
        xs[nl][j] = (n < NN) ? g_h[n * D + j] : 0.f;
    }
    __syncthreads();
    int ng = tid >> 2, cg = tid & 3;
    int c0 = cg * 16;
    float acc[4][16];
#pragma unroll
    for (int i = 0; i < 4; i++)
#pragma unroll
        for (int j = 0; j < 16; j++) acc[i][j] = 0.f;

#pragma unroll 4
    for (int k = 0; k < 32; k++) {
        float xv[4];
#pragma unroll
        for (int i = 0; i < 4; i++) xv[i] = xs[ng * 4 + i][k];
        const float* wrow = &Wsh[k][c0];
        float4 w0 = *(const float4*)&wrow[0];
        float4 w1 = *(const float4*)&wrow[4];
        float4 w2 = *(const float4*)&wrow[8];
        float4 w3 = *(const float4*)&wrow[12];
#pragma unroll
        for (int i = 0; i < 4; i++) {
            float xi = xv[i];
            acc[i][0]  = fmaf(xi, w0.x, acc[i][0]);
            acc[i][1]  = fmaf(xi, w0.y, acc[i][1]);
            acc[i][2]  = fmaf(xi, w0.z, acc[i][2]);
            acc[i][3]  = fmaf(xi, w0.w, acc[i][3]);
            acc[i][4]  = fmaf(xi, w1.x, acc[i][4]);
            acc[i][5]  = fmaf(xi, w1.y, acc[i][5]);
            acc[i][6]  = fmaf(xi, w1.z, acc[i][6]);
            acc[i][7]  = fmaf(xi, w1.w, acc[i][7]);
            acc[i][8]  = fmaf(xi, w2.x, acc[i][8]);
            acc[i][9]  = fmaf(xi, w2.y, acc[i][9]);
            acc[i][10] = fmaf(xi, w2.z, acc[i][10]);
            acc[i][11] = fmaf(xi, w2.w, acc[i][11]);
            acc[i][12] = fmaf(xi, w3.x, acc[i][12]);
            acc[i][13] = fmaf(xi, w3.y, acc[i][13]);
            acc[i][14] = fmaf(xi, w3.z, acc[i][14]);
            acc[i][15] = fmaf(xi, w3.w, acc[i][15]);
        }
    }
#pragma unroll
    for (int i = 0; i < 4; i++) {
        int n = n0 + ng * 4 + i;
        if (n >= NN) break;
        if (cg < 2) {
            store_rhs_fp16(&g_rhsH[n * D + c0], acc[i]);
        } else {
            float* dstp = &g_self[n * D + (c0 - 32)];
#pragma unroll
            for (int j = 0; j < 4; j++) {
                float4 f = make_float4(acc[i][4 * j], acc[i][4 * j + 1],
                                       acc[i][4 * j + 2], acc[i][4 * j + 3]);
                *(float4*)&dstp[4 * j] = f;
            }
        }
    }
}

// ------------------------------------------------------------------
// Aggregation: warp per node; 8 edges per warp-LDG; fp16 pairwise add (HADD2)
// before fp32 accumulate in the 16-edge loop (fewer issue slots).
__device__ __forceinline__ void acc8(uint4 v, float* f) {
    const __half2* h = (const __half2*)&v;
#pragma unroll
    for (int j = 0; j < 4; j++) {
        float2 t = __half22float2(h[j]);
        f[2 * j]     += t.x;
        f[2 * j + 1] += t.y;
    }
}

__device__ __forceinline__ void acc8_pair(uint4 a, uint4 b, float* f) {
    const __half2* ha = (const __half2*)&a;
    const __half2* hb = (const __half2*)&b;
#pragma unroll
    for (int j = 0; j < 4; j++) {
        __half2 s = __hadd2(ha[j], hb[j]);   // 2-way fp16 sum: overflow-safe
        float2 t = __half22float2(s);
        f[2 * j]     += t.x;
        f[2 * j + 1] += t.y;
    }
}

__global__ void __launch_bounds__(256) agg_kernel(const float* __restrict__ bn) {
    int tid = threadIdx.x;
    int w = (blockIdx.x * blockDim.x + tid) >> 5;
    if (w >= NN) return;
    int lane = tid & 31;
    int eg = lane >> 2, q = lane & 3;
    const uint4* __restrict__ rhs4 = (const uint4*)g_rhsH;   // 4 uint4 per row

    int beg = g_offs[w], end = g_offs[w + 1];
    float f[8];
#pragma unroll
    for (int j = 0; j < 8; j++) f[j] = 0.f;

    int e = beg;
    while (e + 16 <= end) {
        int s0 = g_csrc[e + eg];
        int s1 = g_csrc[e + 8 + eg];
        uint4 v0 = rhs4[s0 * 4 + q];
        uint4 v1 = rhs4[s1 * 4 + q];
        acc8_pair(v0, v1, f);
        e += 16;
    }
    while (e + 8 <= end) {
        int s = g_csrc[e + eg];
        uint4 v = rhs4[s * 4 + q];
        acc8(v, f);
        e += 8;
    }
    int rem = end - e;
    if (eg < rem) {
        int s = g_csrc[e + eg];
        uint4 v = rhs4[s * 4 + q];
        acc8(v, f);
    }

#pragma unroll
    for (int j = 0; j < 8; j++) {
        f[j] += __shfl_xor_sync(0xffffffffu, f[j], 4);
        f[j] += __shfl_xor_sync(0xffffffffu, f[j], 8);
        f[j] += __shfl_xor_sync(0xffffffffu, f[j], 16);
    }

    if (lane < 4) {
        int base = w * D + 8 * lane;
        float4 s0 = *(const float4*)&g_self[base];
        float4 s1 = *(const float4*)&g_self[base + 4];
        float4 b0 = *(const float4*)&bn[8 * lane];
        float4 b1 = *(const float4*)&bn[8 * lane + 4];
        float4 o0, o1;
        o0.x = fmaxf(f[0] + s0.x + b0.x, 0.f);
        o0.y = fmaxf(f[1] + s0.y + b0.y, 0.f);
        o0.z = fmaxf(f[2] + s0.z + b0.z, 0.f);
        o0.w = fmaxf(f[3] + s0.w + b0.w, 0.f);
        o1.x = fmaxf(f[4] + s1.x + b1.x, 0.f);
        o1.y = fmaxf(f[5] + s1.y + b1.y, 0.f);
        o1.z = fmaxf(f[6] + s1.z + b1.z, 0.f);
        o1.w = fmaxf(f[7] + s1.w + b1.w, 0.f);
        *(float4*)&g_h[base]     = o0;
        *(float4*)&g_h[base + 4] = o1;
    }
}

// ------------------------------------------------------------------
__global__ void __launch_bounds__(256) pool_kernel(const int* __restrict__ gid) {
    __shared__ float ps[NG * D];
    int tid = threadIdx.x;
    for (int i = tid; i < NG * D; i += 256) ps[i] = 0.f;
    __syncthreads();
    int d = tid & 31;
    int base = blockIdx.x * 1024;
    for (int i = tid >> 5; i < 1024; i += 8) {
        int n = base + i;
        if (n < NN) atomicAdd(&ps[gid[n] * D + d], g_h[n * D + d]);
    }
    __syncthreads();
    for (int i = tid; i < NG * D; i += 256) {
        float v = ps[i];
        if (v != 0.f) atomicAdd(&g_pool[i], v);
    }
}

__global__ void mlp_kernel(const float* __restrict__ Wfc1, const float* __restrict__ bfc1,
                           const float* __restrict__ Wout, const float* __restrict__ bout,
                           float* __restrict__ out) {
    int g = threadIdx.x;
    if (g >= NG) return;
    float hv[D];
#pragma unroll
    for (int k = 0; k < D; k++) hv[k] = g_pool[g * D + k];
    float h2[8];
#pragma unroll
    for (int j = 0; j < 8; j++) {
        float s = bfc1[j];
#pragma unroll
        for (int k = 0; k < D; k++) s = fmaf(hv[k], Wfc1[k * 8 + j], s);
        h2[j] = fmaxf(s, 0.f);
    }
    float o[4];
    float m = -1e30f;
#pragma unroll
    for (int j = 0; j < 4; j++) {
        float s = bout[j];
#pragma unroll
        for (int k = 0; k < 8; k++) s = fmaf(h2[k], Wout[k * 4 + j], s);
        o[j] = fmaxf(s, 0.f);
        if (o[j] > m) m = o[j];
    }
    float e[4]; float sum = 0.f;
#pragma unroll
    for (int j = 0; j < 4; j++) { e[j] = expf(o[j] - m); sum += e[j]; }
#pragma unroll
    for (int j = 0; j < 4; j++) out[g * 4 + j] = e[j] / sum;
}

// ------------------------------------------------------------------
extern "C" void kernel_launch(void* const* d_in, const int* in_sizes, int n_in,
                              void* d_out, int out_size) {
    const float* x    = (const float*)d_in[0];
    const float* Wn0  = (const float*)d_in[1];
    const float* bn0  = (const float*)d_in[2];
    const float* Ws0  = (const float*)d_in[3];
    const float* Wn   = (const float*)d_in[4];
    const float* bn   = (const float*)d_in[5];
    const float* Ws   = (const float*)d_in[6];
    const float* Wfc1 = (const float*)d_in[7];
    const float* bfc1 = (const float*)d_in[8];
    const float* Wout = (const float*)d_in[9];
    const float* bout = (const float*)d_in[10];
    const int*   src  = (const int*)d_in[11];
    const int*   dst  = (const int*)d_in[12];
    const int*   gid  = (const int*)d_in[13];
    float* out = (float*)d_out;

    // Fork a side stream so the CSR build (hist -> scan -> scatter, ~94us)
    // overlaps gemm0 (~99us) on the main stream. Created fresh per call
    // (kernel_launch runs only for correctness + capture; graph replays do
    // not re-enter). Event record/wait is the documented capture-fork pattern.
    cudaStream_t s2;
    cudaEvent_t ev_fork, ev_join;
    cudaStreamCreateWithFlags(&s2, cudaStreamNonBlocking);
    cudaEventCreateWithFlags(&ev_fork, cudaEventDisableTiming);
    cudaEventCreateWithFlags(&ev_join, cudaEventDisableTiming);

    cudaEventRecord(ev_fork, 0);
    cudaStreamWaitEvent(s2, ev_fork, 0);

    // side stream: CSR build
    hist_kernel<<<(NE / 4 + 255) / 256, 256, 0, s2>>>(dst);
    scan_all<<<1, 1024, 0, s2>>>();
    scatter_kernel<<<(NE / 4 + 255) / 256, 256, 0, s2>>>(src, dst);
    cudaEventRecord(ev_join, s2);

    // main stream: layer-0 transform (independent of CSR)
    gemm0_kernel<<<(NN + 63) / 64, 64>>>(x, Wn0, Ws0);

    // join: agg needs both rhsH/self (main) and csrc/offs (side)
    cudaStreamWaitEvent(0, ev_join, 0);

    agg_kernel<<<(NN * 32 + 255) / 256, 256>>>(bn0);
    for (int l = 0; l < 3; l++) {
        gemm_small_kernel<<<(NN + 63) / 64, 64>>>(Wn + l * D * D, Ws + l * D * D);
        agg_kernel<<<(NN * 32 + 255) / 256, 256>>>(bn + l * D);
    }

    pool_kernel<<<(NN + 1023) / 1024, 256>>>(gid);
    mlp_kernel<<<1, 64>>>(Wfc1, bfc1, Wout, bout, out);
    // stream/events intentionally not destroyed: destroying a capturing
    // stream mid-capture is illegal; ~3 total calls leak trivially.
}

// round 14
// speedup vs baseline: 1.3584x; 1.3030x over previous
#include <cuda_runtime.h>
#include <cuda_fp16.h>
#include <math.h>

#define NN 100000
#define NE 3200000
#define NG 64
#define D 32
#define INF 128
#define NPAD 102400   // 1024 threads * 100 counters

// ---- scratch (zero-initialized at module load; scan_all re-zeros per call) ----
__device__ __half g_rhsH[NN * D];   // fp16 gather buffer (64B rows)
__device__ float  g_self[NN * D];
__device__ float  g_h[NN * D];
__device__ float  g_pool[NG * D];
__device__ int    g_counts[NPAD];
__device__ int    g_offs[NPAD + 1];
__device__ int    g_cursor[NPAD];
__device__ int    g_csrc[NE];

// ------------------------------------------------------------------
__global__ void hist_kernel(const int* __restrict__ dst) {
    int i = blockIdx.x * blockDim.x + threadIdx.x;
    int b = i * 4;
    if (b < NE) {
        int4 d = *(const int4*)&dst[b];
        atomicAdd(&g_counts[d.x], 1);
        atomicAdd(&g_counts[d.y], 1);
        atomicAdd(&g_counts[d.z], 1);
        atomicAdd(&g_counts[d.w], 1);
    }
}

// single-block scan; also re-zeros g_counts and zeros g_pool for this call.
__global__ void __launch_bounds__(1024) scan_all() {
    const int CH = 100;
    int tid = threadIdx.x;
    int lane = tid & 31, wid = tid >> 5;
    int base = tid * CH;
    int s = 0;
    int cnt[CH];
#pragma unroll
    for (int i = 0; i < CH; i += 4) {
        int4 v = *(const int4*)&g_counts[base + i];
        cnt[i] = v.x; cnt[i + 1] = v.y; cnt[i + 2] = v.z; cnt[i + 3] = v.w;
        s += v.x + v.y + v.z + v.w;
    }
    int pre = s;
#pragma unroll
    for (int dd = 1; dd < 32; dd <<= 1) {
        int t = __shfl_up_sync(0xffffffffu, pre, dd);
        if (lane >= dd) pre += t;
    }
    __shared__ int wsum[32];
    if (lane == 31) wsum[wid] = pre;
    __syncthreads();
    if (wid == 0) {
        int v = wsum[lane];
        int p = v;
#pragma unroll
        for (int dd = 1; dd < 32; dd <<= 1) {
            int t = __shfl_up_sync(0xffffffffu, p, dd);
            if (lane >= dd) p += t;
        }
        wsum[lane] = p - v;
    }
    __syncthreads();
    int run = wsum[wid] + (pre - s);
    const int4 z4 = make_int4(0, 0, 0, 0);
#pragma unroll
    for (int i = 0; i < CH; i += 4) {
        int4 o;
        o.x = run; run += cnt[i];
        o.y = run; run += cnt[i + 1];
        o.z = run; run += cnt[i + 2];
        o.w = run; run += cnt[i + 3];
        *(int4*)&g_offs[base + i]   = o;
        *(int4*)&g_cursor[base + i] = o;
        *(int4*)&g_counts[base + i] = z4;
    }
    if (tid < NG * D / 2) *(float2*)&g_pool[tid * 2] = make_float2(0.f, 0.f);
}

__global__ void scatter_kernel(const int* __restrict__ src, const int* __restrict__ dst) {
    int i = blockIdx.x * blockDim.x + threadIdx.x;
    int b = i * 4;
    if (b < NE) {
        int4 s4 = *(const int4*)&src[b];
        int4 d4 = *(const int4*)&dst[b];
        int p;
        p = atomicAdd(&g_cursor[d4.x], 1); g_csrc[p] = s4.x;
        p = atomicAdd(&g_cursor[d4.y], 1); g_csrc[p] = s4.y;
        p = atomicAdd(&g_cursor[d4.z], 1); g_csrc[p] = s4.z;
        p = atomicAdd(&g_cursor[d4.w], 1); g_csrc[p] = s4.w;
    }
}

// ------------------------------------------------------------------
// fp16 GEMM core: thread owns 4 nodes x 16 cols as 4x8 half2 accumulators.
// Per k-step: 4 xs2 LDS.32 (broadcast half2) + 2 uint4 W loads + 32 HFMA2.
// ng = tid>>2 (node group), cg = tid&3 (col group; cg<2 -> rhs, cg>=2 -> self).
__device__ __forceinline__ void hgemm_ktile(const __half2 xs2[64][33],
                                            const __half2 Wsh2[32][32],
                                            int ng, int cg, __half2 acc2[4][8]) {
#pragma unroll 4
    for (int k = 0; k < 32; k++) {
        __half2 xh[4];
#pragma unroll
        for (int i = 0; i < 4; i++) xh[i] = xs2[ng * 4 + i][k];
        __align__(16) __half2 w2[8];
        const uint4* wp = (const uint4*)&Wsh2[k][cg * 8];
        *(uint4*)&w2[0] = wp[0];
        *(uint4*)&w2[4] = wp[1];
#pragma unroll
        for (int i = 0; i < 4; i++)
#pragma unroll
            for (int j = 0; j < 8; j++)
                acc2[i][j] = __hfma2(xh[i], w2[j], acc2[i][j]);
    }
}

__device__ __forceinline__ void hgemm_store(int n0, int ng, int cg, __half2 acc2[4][8]) {
    int c0 = cg * 16;
#pragma unroll
    for (int i = 0; i < 4; i++) {
        int n = n0 + ng * 4 + i;
        if (n >= NN) break;
        if (cg < 2) {
            // cols c0..c0+15 as fp16: 8 half2 = two uint4 stores
            *(uint4*)&g_rhsH[n * D + c0]     = *(uint4*)&acc2[i][0];
            *(uint4*)&g_rhsH[n * D + c0 + 8] = *(uint4*)&acc2[i][4];
        } else {
            float* dstp = &g_self[n * D + (c0 - 32)];
#pragma unroll
            for (int j = 0; j < 4; j++) {
                float2 a = __half22float2(acc2[i][2 * j]);
                float2 b = __half22float2(acc2[i][2 * j + 1]);
                *(float4*)&dstp[4 * j] = make_float4(a.x, a.y, b.x, b.y);
            }
        }
    }
}

// Layer 0: rhsH = fp16(x@Wn0), self = x@Ws0.  64 thr, 64 nodes/block.
__global__ void __launch_bounds__(64, 12) gemm0_kernel(const float* __restrict__ x,
                                                       const float* __restrict__ Wn0,
                                                       const float* __restrict__ Ws0) {
    __shared__ __half2 Wsh2[32][32];   // k x 32 half2 (cols 0..31 Wn, 32..63 Ws)
    __shared__ __half2 xs2[64][33];    // broadcast pairs (v,v)
    int tid = threadIdx.x;
    int n0 = blockIdx.x * 64;
    int ng = tid >> 2, cg = tid & 3;
    __half2 acc2[4][8];
#pragma unroll
    for (int i = 0; i < 4; i++)
#pragma unroll
        for (int j = 0; j < 8; j++) acc2[i][j] = __float2half2_rn(0.f);

    for (int kt = 0; kt < 4; kt++) {
        __syncthreads();
        // stage W k-tile: 32 k x 32 half2; c2<16 from Wn0, else Ws0
        for (int idx = tid; idx < 32 * 32; idx += 64) {
            int k = idx >> 5, c2 = idx & 31;
            const float* srcw = (c2 < 16) ? &Wn0[kt * 1024 + k * 32 + 2 * c2]
                                          : &Ws0[kt * 1024 + k * 32 + 2 * (c2 - 16)];
            float2 wv = *(const float2*)srcw;
            Wsh2[k][c2] = __floats2half2_rn(wv.x, wv.y);
        }
        // stage x tile (broadcast half2)
        for (int idx = tid; idx < 64 * 32; idx += 64) {
            int nl = idx >> 5, j = idx & 31;
            int n = n0 + nl;
            float v = (n < NN) ? x[n * INF + kt * 32 + j] : 0.f;
            xs2[nl][j] = __float2half2_rn(v);
        }
        __syncthreads();
        hgemm_ktile(xs2, Wsh2, ng, cg, acc2);
    }
    hgemm_store(n0, ng, cg, acc2);
}

// Layers 1..3: rhsH = fp16(h@Wn_l), self = h@Ws_l  (K=32, input g_h).
__global__ void __launch_bounds__(64, 12) gemm_small_kernel(const float* __restrict__ Wn_l,
                                                            const float* __restrict__ Ws_l) {
    __shared__ __half2 Wsh2[32][32];
    __shared__ __half2 xs2[64][33];
    int tid = threadIdx.x;
    int n0 = blockIdx.x * 64;
    for (int idx = tid; idx < 32 * 32; idx += 64) {
        int k = idx >> 5, c2 = idx & 31;
        const float* srcw = (c2 < 16) ? &Wn_l[k * 32 + 2 * c2]
                                      : &Ws_l[k * 32 + 2 * (c2 - 16)];
        float2 wv = *(const float2*)srcw;
        Wsh2[k][c2] = __floats2half2_rn(wv.x, wv.y);
    }
    for (int idx = tid; idx < 64 * 32; idx += 64) {
        int nl = idx >> 5, j = idx & 31;
        int n = n0 + nl;
        float v = (n < NN) ? g_h[n * D + j] : 0.f;
        xs2[nl][j] = __float2half2_rn(v);
    }
    __syncthreads();
    int ng = tid >> 2, cg = tid & 3;
    __half2 acc2[4][8];
#pragma unroll
    for (int i = 0; i < 4; i++)
#pragma unroll
        for (int j = 0; j < 8; j++) acc2[i][j] = __float2half2_rn(0.f);
    hgemm_ktile(xs2, Wsh2, ng, cg, acc2);
    hgemm_store(n0, ng, cg, acc2);
}

// ------------------------------------------------------------------
// Aggregation (R12-profiled, R13 HADD2): warp per node; 8 edges per warp-LDG.
__device__ __forceinline__ void acc8(uint4 v, float* f) {
    const __half2* h = (const __half2*)&v;
#pragma unroll
    for (int j = 0; j < 4; j++) {
        float2 t = __half22float2(h[j]);
        f[2 * j]     += t.x;
        f[2 * j + 1] += t.y;
    }
}

__device__ __forceinline__ void acc8_pair(uint4 a, uint4 b, float* f) {
    const __half2* ha = (const __half2*)&a;
    const __half2* hb = (const __half2*)&b;
#pragma unroll
    for (int j = 0; j < 4; j++) {
        __half2 s = __hadd2(ha[j], hb[j]);   // 2-way fp16 sum: overflow-safe
        float2 t = __half22float2(s);
        f[2 * j]     += t.x;
        f[2 * j + 1] += t.y;
    }
}

__global__ void __launch_bounds__(256) agg_kernel(const float* __restrict__ bn) {
    int tid = threadIdx.x;
    int w = (blockIdx.x * blockDim.x + tid) >> 5;
    if (w >= NN) return;
    int lane = tid & 31;
    int eg = lane >> 2, q = lane & 3;
    const uint4* __restrict__ rhs4 = (const uint4*)g_rhsH;

    int beg = g_offs[w], end = g_offs[w + 1];
    float f[8];
#pragma unroll
    for (int j = 0; j < 8; j++) f[j] = 0.f;

    int e = beg;
    while (e + 16 <= end) {
        int s0 = g_csrc[e + eg];
        int s1 = g_csrc[e + 8 + eg];
        uint4 v0 = rhs4[s0 * 4 + q];
        uint4 v1 = rhs4[s1 * 4 + q];
        acc8_pair(v0, v1, f);
        e += 16;
    }
    while (e + 8 <= end) {
        int s = g_csrc[e + eg];
        uint4 v = rhs4[s * 4 + q];
        acc8(v, f);
        e += 8;
    }
    int rem = end - e;
    if (eg < rem) {
        int s = g_csrc[e + eg];
        uint4 v = rhs4[s * 4 + q];
        acc8(v, f);
    }

#pragma unroll
    for (int j = 0; j < 8; j++) {
        f[j] += __shfl_xor_sync(0xffffffffu, f[j], 4);
        f[j] += __shfl_xor_sync(0xffffffffu, f[j], 8);
        f[j] += __shfl_xor_sync(0xffffffffu, f[j], 16);
    }

    if (lane < 4) {
        int base = w * D + 8 * lane;
        float4 s0 = *(const float4*)&g_self[base];
        float4 s1 = *(const float4*)&g_self[base + 4];
        float4 b0 = *(const float4*)&bn[8 * lane];
        float4 b1 = *(const float4*)&bn[8 * lane + 4];
        float4 o0, o1;
        o0.x = fmaxf(f[0] + s0.x + b0.x, 0.f);
        o0.y = fmaxf(f[1] + s0.y + b0.y, 0.f);
        o0.z = fmaxf(f[2] + s0.z + b0.z, 0.f);
        o0.w = fmaxf(f[3] + s0.w + b0.w, 0.f);
        o1.x = fmaxf(f[4] + s1.x + b1.x, 0.f);
        o1.y = fmaxf(f[5] + s1.y + b1.y, 0.f);
        o1.z = fmaxf(f[6] + s1.z + b1.z, 0.f);
        o1.w = fmaxf(f[7] + s1.w + b1.w, 0.f);
        *(float4*)&g_h[base]     = o0;
        *(float4*)&g_h[base + 4] = o1;
    }
}

// ------------------------------------------------------------------
__global__ void __launch_bounds__(256) pool_kernel(const int* __restrict__ gid) {
    __shared__ float ps[NG * D];
    int tid = threadIdx.x;
    for (int i = tid; i < NG * D; i += 256) ps[i] = 0.f;
    __syncthreads();
    int d = tid & 31;
    int base = blockIdx.x * 1024;
    for (int i = tid >> 5; i < 1024; i += 8) {
        int n = base + i;
        if (n < NN) atomicAdd(&ps[gid[n] * D + d], g_h[n * D + d]);
    }
    __syncthreads();
    for (int i = tid; i < NG * D; i += 256) {
        float v = ps[i];
        if (v != 0.f) atomicAdd(&g_pool[i], v);
    }
}

__global__ void mlp_kernel(const float* __restrict__ Wfc1, const float* __restrict__ bfc1,
                           const float* __restrict__ Wout, const float* __restrict__ bout,
                           float* __restrict__ out) {
    int g = threadIdx.x;
    if (g >= NG) return;
    float hv[D];
#pragma unroll
    for (int k = 0; k < D; k++) hv[k] = g_pool[g * D + k];
    float h2[8];
#pragma unroll
    for (int j = 0; j < 8; j++) {
        float s = bfc1[j];
#pragma unroll
        for (int k = 0; k < D; k++) s = fmaf(hv[k], Wfc1[k * 8 + j], s);
        h2[j] = fmaxf(s, 0.f);
    }
    float o[4];
    float m = -1e30f;
#pragma unroll
    for (int j = 0; j < 4; j++) {
        float s = bout[j];
#pragma unroll
        for (int k = 0; k < 8; k++) s = fmaf(h2[k], Wout[k * 4 + j], s);
        o[j] = fmaxf(s, 0.f);
        if (o[j] > m) m = o[j];
    }
    float e[4]; float sum = 0.f;
#pragma unroll
    for (int j = 0; j < 4; j++) { e[j] = expf(o[j] - m); sum += e[j]; }
#pragma unroll
    for (int j = 0; j < 4; j++) out[g * 4 + j] = e[j] / sum;
}

// ------------------------------------------------------------------
extern "C" void kernel_launch(void* const* d_in, const int* in_sizes, int n_in,
                              void* d_out, int out_size) {
    const float* x    = (const float*)d_in[0];
    const float* Wn0  = (const float*)d_in[1];
    const float* bn0  = (const float*)d_in[2];
    const float* Ws0  = (const float*)d_in[3];
    const float* Wn   = (const float*)d_in[4];
    const float* bn   = (const float*)d_in[5];
    const float* Ws   = (const float*)d_in[6];
    const float* Wfc1 = (const float*)d_in[7];
    const float* bfc1 = (const float*)d_in[8];
    const float* Wout = (const float*)d_in[9];
    const float* bout = (const float*)d_in[10];
    const int*   src  = (const int*)d_in[11];
    const int*   dst  = (const int*)d_in[12];
    const int*   gid  = (const int*)d_in[13];
    float* out = (float*)d_out;

    // Fork a side stream so the CSR build overlaps gemm0 (lower gemm0
    // occupancy demand this round leaves real room for co-scheduling).
    cudaStream_t s2;
    cudaEvent_t ev_fork, ev_join;
    cudaStreamCreateWithFlags(&s2, cudaStreamNonBlocking);
    cudaEventCreateWithFlags(&ev_fork, cudaEventDisableTiming);
    cudaEventCreateWithFlags(&ev_join, cudaEventDisableTiming);

    cudaEventRecord(ev_fork, 0);
    cudaStreamWaitEvent(s2, ev_fork, 0);

    hist_kernel<<<(NE / 4 + 255) / 256, 256, 0, s2>>>(dst);
    scan_all<<<1, 1024, 0, s2>>>();
    scatter_kernel<<<(NE / 4 + 255) / 256, 256, 0, s2>>>(src, dst);
    cudaEventRecord(ev_join, s2);

    gemm0_kernel<<<(NN + 63) / 64, 64>>>(x, Wn0, Ws0);

    cudaStreamWaitEvent(0, ev_join, 0);

    agg_kernel<<<(NN * 32 + 255) / 256, 256>>>(bn0);
    for (int l = 0; l < 3; l++) {
        gemm_small_kernel<<<(NN + 63) / 64, 64>>>(Wn + l * D * D, Ws + l * D * D);
        agg_kernel<<<(NN * 32 + 255) / 256, 256>>>(bn + l * D);
    }

    pool_kernel<<<(NN + 1023) / 1024, 256>>>(gid);
    mlp_kernel<<<1, 64>>>(Wfc1, bfc1, Wout, bout, out);
    // stream/events intentionally not destroyed (capture-safe; ~3 calls total)
}